// round 3
// baseline (speedup 1.0000x reference)
#include <cuda_runtime.h>
#include <cfloat>
#include <math.h>

// ---------------------------------------------------------------------------
// AttentionLayer: inputs[2048,1024] -> out[2048,2048]
// Exploits exact structure of the "scores * mask" reference:
//   m_s False row -> exact uniform softmax -> out = xmean @ Wv + bv
//   m_s True  row -> exact one-hot at argmin_t raw_score over m_t True
// All heavy math fp32 via packed fma.rn.f32x2 (2 FMA/instr on sm_103a).
// ---------------------------------------------------------------------------

#define SEQ   2048
#define DM    1024
#define NQ    2048   // NUM_HEADS * 128
#define HN    16
#define HD    128

// scratch (static __device__ -- no allocations allowed)
__device__ float g_Qc[(size_t)SEQ * NQ];   // compacted-row projections
__device__ float g_Kc[(size_t)SEQ * NQ];
__device__ float g_Vc[(size_t)SEQ * NQ];
__device__ int   g_cidx[SEQ];              // compacted -> original index
__device__ int   g_mask[SEQ];
__device__ int   g_cnt;
__device__ int   g_argT[HN * SEQ];         // per (head, ORIGINAL s): compacted t index
__device__ float g_xmean[DM];
__device__ float g_vmean[NQ];

typedef unsigned long long ull;

__device__ __forceinline__ ull pk2(float lo, float hi) {
    ull r; asm("mov.b64 %0, {%1, %2};" : "=l"(r) : "f"(lo), "f"(hi)); return r;
}
__device__ __forceinline__ void upk2(ull v, float& lo, float& hi) {
    asm("mov.b64 {%0, %1}, %2;" : "=f"(lo), "=f"(hi) : "l"(v));
}
__device__ __forceinline__ ull ffma2(ull a, ull b, ull c) {
    ull d; asm("fma.rn.f32x2 %0, %1, %2, %3;" : "=l"(d) : "l"(a), "l"(b), "l"(c)); return d;
}

// ---------------------------------------------------------------------------
// prep: sniff mask dtype, expand mask, stable-compact true indices
// ---------------------------------------------------------------------------
__global__ void prep_kernel(const unsigned int* mraw) {
    __shared__ int sm[SEQ];
    __shared__ int flag_f, flag_not01;
    int tid = threadIdx.x;
    if (tid == 0) { flag_f = 0; flag_not01 = 0; }
    __syncthreads();
    if (tid < 512) {
        unsigned w = mraw[tid];               // first 2048 bytes: safe for all dtypes
        if (w == 0x3F800000u) atomicOr(&flag_f, 1);
        if (w > 1u)           atomicOr(&flag_not01, 1);
    }
    __syncthreads();
    int kind = flag_f ? 2 : (flag_not01 ? 0 : 1);   // 0=byte bool, 1=int32, 2=float32
    for (int i = tid; i < SEQ; i += 1024) {
        int v;
        if (kind == 0)      v = (((const unsigned char*)mraw)[i] != 0);
        else if (kind == 1) v = (((const int*)mraw)[i] != 0);
        else                v = (((const float*)mraw)[i] != 0.0f);
        sm[i] = v; g_mask[i] = v;
    }
    __syncthreads();
    if (tid == 0) {
        int c = 0;
        for (int i = 0; i < SEQ; i++) if (sm[i]) g_cidx[c++] = i;
        g_cnt = c;
    }
}

// ---------------------------------------------------------------------------
// column mean of inputs (for the uniform-softmax rows)
// ---------------------------------------------------------------------------
__global__ void xmean_kernel(const float* __restrict__ inp) {
    int k = blockIdx.x * 256 + threadIdx.x;   // 0..1023
    float s = 0.0f;
    for (int i = 0; i < SEQ; i++) s += inp[(size_t)i * DM + k];
    g_xmean[k] = s * (1.0f / 2048.0f);
}

__global__ void vmean_kernel(const float* __restrict__ Wv, const float* __restrict__ bv) {
    int c = blockIdx.x * 256 + threadIdx.x;   // 0..2047
    float s = 0.0f;
    for (int k = 0; k < DM; k++) s += g_xmean[k] * Wv[(size_t)k * NQ + c];
    g_vmean[c] = s + bv[c];
}

// ---------------------------------------------------------------------------
// Projection GEMM: Cc[j, n] = inputs[cidx[j], :] @ W[:, n] + b[n]
// grid (Ntiles=16, Mtiles=16, z=3 for Q/K/V), 256 thr, 128x128x16 tile,
// 8x8 micro via f32x2 (pairs along n).
// ---------------------------------------------------------------------------
__global__ __launch_bounds__(256) void proj_kernel(
    const float* __restrict__ inp,
    const float* __restrict__ Wq, const float* __restrict__ Wk, const float* __restrict__ Wv,
    const float* __restrict__ bq, const float* __restrict__ bk, const float* __restrict__ bv)
{
    int cnt = g_cnt;
    int m0 = blockIdx.y * 128;
    if (m0 >= cnt) return;
    int n0 = blockIdx.x * 128;
    int z  = blockIdx.z;
    const float* W    = (z == 0) ? Wq : (z == 1) ? Wk : Wv;
    const float* bias = (z == 0) ? bq : (z == 1) ? bk : bv;
    float*       out  = (z == 0) ? g_Qc : (z == 1) ? g_Kc : g_Vc;

    __shared__ float As[16][132];   // [k][m]
    __shared__ float Bs[16][132];   // [k][n]
    __shared__ int   cid[128];

    int tid = threadIdx.x, tx = tid & 15, ty = tid >> 4;
    if (tid < 128) cid[tid] = g_cidx[min(m0 + tid, cnt - 1)];

    ull acc[8][4];
    #pragma unroll
    for (int i = 0; i < 8; i++)
        #pragma unroll
        for (int j = 0; j < 4; j++) acc[i][j] = 0ull;

    for (int kt = 0; kt < 64; kt++) {
        int k0 = kt * 16;
        __syncthreads();
        // A tile 128 rows x 16 k (gathered rows)
        #pragma unroll
        for (int it = 0; it < 2; it++) {
            int idx = it * 256 + tid;
            int k4 = idx >> 7, row = idx & 127;
            float4 v = *(const float4*)&inp[(size_t)cid[row] * DM + k0 + k4 * 4];
            As[k4 * 4 + 0][row] = v.x; As[k4 * 4 + 1][row] = v.y;
            As[k4 * 4 + 2][row] = v.z; As[k4 * 4 + 3][row] = v.w;
        }
        // B tile 16 k x 128 n (coalesced)
        #pragma unroll
        for (int it = 0; it < 2; it++) {
            int idx = it * 256 + tid;
            int n4 = idx & 31, k = idx >> 5;
            *(float4*)&Bs[k][n4 * 4] =
                *(const float4*)&W[(size_t)(k0 + k) * NQ + n0 + n4 * 4];
        }
        __syncthreads();
        #pragma unroll
        for (int k = 0; k < 16; k++) {
            float4 aA = *(const float4*)&As[k][ty * 8];
            float4 aB = *(const float4*)&As[k][ty * 8 + 4];
            ulonglong2 b01 = *(const ulonglong2*)&Bs[k][tx * 8];
            ulonglong2 b23 = *(const ulonglong2*)&Bs[k][tx * 8 + 4];
            float av[8] = {aA.x, aA.y, aA.z, aA.w, aB.x, aB.y, aB.z, aB.w};
            #pragma unroll
            for (int i = 0; i < 8; i++) {
                ull ai = pk2(av[i], av[i]);
                acc[i][0] = ffma2(ai, b01.x, acc[i][0]);
                acc[i][1] = ffma2(ai, b01.y, acc[i][1]);
                acc[i][2] = ffma2(ai, b23.x, acc[i][2]);
                acc[i][3] = ffma2(ai, b23.y, acc[i][3]);
            }
        }
    }
    int base_n = n0 + tx * 8;
    #pragma unroll
    for (int i = 0; i < 8; i++) {
        int m = m0 + ty * 8 + i;
        if (m >= cnt) continue;
        float* orow = &out[(size_t)m * NQ + base_n];
        #pragma unroll
        for (int j = 0; j < 4; j++) {
            float lo, hi; upk2(acc[i][j], lo, hi);
            float2 bb = *(const float2*)&bias[base_n + 2 * j];
            float2 r; r.x = lo + bb.x; r.y = hi + bb.y;
            *(float2*)&orow[2 * j] = r;
        }
    }
}

// ---------------------------------------------------------------------------
// QK^T + running argmin, per (head, s-tile of 64 compacted rows).
// Q tile resident in smem [d][s]; K streamed in 16-d chunks [d][t].
// 4x8 micro via f32x2 (pairs along t). Writes g_argT[h][orig_s] = compacted t*.
// ---------------------------------------------------------------------------
__global__ __launch_bounds__(256) void qk_kernel() {
    __shared__ float Qs[128][68];     // [d][s]
    __shared__ float Ks[16][132];     // [d][t]
    int cnt = g_cnt;
    int s0 = blockIdx.x * 64;
    if (s0 >= cnt) return;
    int h = blockIdx.y;
    int hb = h * HD;
    int tid = threadIdx.x, tx = tid & 15, ty = tid >> 4;

    // load Q tile (64 s x 128 d), transposed into smem
    #pragma unroll
    for (int it = 0; it < 8; it++) {
        int idx = it * 256 + tid;
        int d4 = idx >> 6, row = idx & 63;
        int r = min(s0 + row, cnt - 1);
        float4 v = *(const float4*)&g_Qc[(size_t)r * NQ + hb + d4 * 4];
        Qs[d4 * 4 + 0][row] = v.x; Qs[d4 * 4 + 1][row] = v.y;
        Qs[d4 * 4 + 2][row] = v.z; Qs[d4 * 4 + 3][row] = v.w;
    }

    float rmin[4] = {FLT_MAX, FLT_MAX, FLT_MAX, FLT_MAX};
    int   ridx[4] = {0, 0, 0, 0};

    int ttiles = (cnt + 127) >> 7;
    for (int tt = 0; tt < ttiles; tt++) {
        int t0 = tt * 128;
        ull acc[4][4];
        #pragma unroll
        for (int i = 0; i < 4; i++)
            #pragma unroll
            for (int j = 0; j < 4; j++) acc[i][j] = 0ull;

        for (int dc = 0; dc < 8; dc++) {
            __syncthreads();
            #pragma unroll
            for (int it = 0; it < 2; it++) {
                int idx = it * 256 + tid;
                int d4 = idx >> 7, row = idx & 127;
                int r = min(t0 + row, cnt - 1);
                float4 v = *(const float4*)&g_Kc[(size_t)r * NQ + hb + dc * 16 + d4 * 4];
                Ks[d4 * 4 + 0][row] = v.x; Ks[d4 * 4 + 1][row] = v.y;
                Ks[d4 * 4 + 2][row] = v.z; Ks[d4 * 4 + 3][row] = v.w;
            }
            __syncthreads();
            #pragma unroll
            for (int k = 0; k < 16; k++) {
                float4 a = *(const float4*)&Qs[dc * 16 + k][ty * 4];
                ulonglong2 b01 = *(const ulonglong2*)&Ks[k][tx * 8];
                ulonglong2 b23 = *(const ulonglong2*)&Ks[k][tx * 8 + 4];
                float av[4] = {a.x, a.y, a.z, a.w};
                #pragma unroll
                for (int i = 0; i < 4; i++) {
                    ull ai = pk2(av[i], av[i]);
                    acc[i][0] = ffma2(ai, b01.x, acc[i][0]);
                    acc[i][1] = ffma2(ai, b01.y, acc[i][1]);
                    acc[i][2] = ffma2(ai, b23.x, acc[i][2]);
                    acc[i][3] = ffma2(ai, b23.y, acc[i][3]);
                }
            }
        }
        // fold this tile's scores into the running argmin (only valid t)
        #pragma unroll
        for (int i = 0; i < 4; i++) {
            #pragma unroll
            for (int j = 0; j < 4; j++) {
                float lo, hi; upk2(acc[i][j], lo, hi);
                int c0 = t0 + tx * 8 + 2 * j;
                if (c0 < cnt     && lo < rmin[i]) { rmin[i] = lo; ridx[i] = c0; }
                if (c0 + 1 < cnt && hi < rmin[i]) { rmin[i] = hi; ridx[i] = c0 + 1; }
            }
        }
    }

    // cross-thread (tx) reduction per s row, reusing Qs memory
    __syncthreads();
    float* Rm = &Qs[0][0];          // 64*16 floats
    int*   Ri = (int*)&Qs[32][0];   // 64*16 ints (disjoint region)
    #pragma unroll
    for (int i = 0; i < 4; i++) {
        Rm[(ty * 4 + i) * 16 + tx] = rmin[i];
        Ri[(ty * 4 + i) * 16 + tx] = ridx[i];
    }
    __syncthreads();
    if (tid < 64) {
        int srow = s0 + tid;
        if (srow < cnt) {
            float bm = Rm[tid * 16]; int bi = Ri[tid * 16];
            #pragma unroll
            for (int x = 1; x < 16; x++) {
                float v = Rm[tid * 16 + x];
                if (v < bm) { bm = v; bi = Ri[tid * 16 + x]; }
            }
            g_argT[h * SEQ + g_cidx[srow]] = bi;
        }
    }
}

// ---------------------------------------------------------------------------
// output: masked rows gather V[t*], unmasked rows take vmean
// ---------------------------------------------------------------------------
__global__ void out_kernel(float* __restrict__ out) {
    int s = blockIdx.x, tid = threadIdx.x;
    int ms = g_mask[s];
    #pragma unroll
    for (int rep = 0; rep < 2; rep++) {
        int c = (rep * 256 + tid) * 4;
        float4 v;
        if (ms) {
            int hh = c >> 7;
            int tc = g_argT[hh * SEQ + s];
            v = *(const float4*)&g_Vc[(size_t)tc * NQ + c];
        } else {
            v = *(const float4*)&g_vmean[c];
        }
        *(float4*)&out[(size_t)s * NQ + c] = v;
    }
}

// ---------------------------------------------------------------------------
extern "C" void kernel_launch(void* const* d_in, const int* in_sizes, int n_in,
                              void* d_out, int out_size)
{
    const float* inp = (const float*)d_in[0];
    const void*  msk = d_in[1];
    const float* Wq  = (const float*)d_in[2];
    const float* bq  = (const float*)d_in[3];
    const float* Wk  = (const float*)d_in[4];
    const float* bk  = (const float*)d_in[5];
    const float* Wv  = (const float*)d_in[6];
    const float* bv  = (const float*)d_in[7];
    float* out = (float*)d_out;

    prep_kernel<<<1, 1024>>>((const unsigned int*)msk);
    xmean_kernel<<<DM / 256, 256>>>(inp);
    proj_kernel<<<dim3(16, 16, 3), 256>>>(inp, Wq, Wk, Wv, bq, bk, bv);
    vmean_kernel<<<NQ / 256, 256>>>(Wv, bv);
    qk_kernel<<<dim3(32, 16), 256>>>();
    out_kernel<<<SEQ, 256>>>(out);
}

// round 9
// speedup vs baseline: 1.3774x; 1.3774x over previous
#include <cuda_runtime.h>
#include <cuda_bf16.h>
#include <cfloat>
#include <cstdint>
#include <math.h>

// ---------------------------------------------------------------------------
// AttentionLayer: inputs[2048,1024] -> out[2048,2048]
//   m_s False row -> exact uniform softmax -> out = xmean @ Wv + bv
//   m_s True  row -> exact one-hot at argmin_t raw_score over m_t True
// Projections: bf16 3-term split on mma.sync (HMMA) -- tcgen05 PTX is rejected
// by this harness's ptxas target (sm_103 without 'a').
// QK^T+argmin in fp32 FFMA2 (precision-critical ordering).
// ---------------------------------------------------------------------------

#define SEQ   2048
#define DM    1024
#define NQ    2048
#define HN    16
#define HD    128

__device__ float g_Qc[(size_t)SEQ * NQ];
__device__ float g_Kc[(size_t)SEQ * NQ];
__device__ float g_Vc[(size_t)SEQ * NQ];
__device__ int   g_cidx[SEQ];
__device__ int   g_mask[SEQ];
__device__ int   g_cnt;
__device__ int   g_argT[HN * SEQ];
__device__ float g_xmean[DM];
__device__ float g_vmean[NQ];
// bf16 3-term splits
__device__ __nv_bfloat16 g_xp[3][(size_t)SEQ * DM];          // x parts [s][k]
__device__ __nv_bfloat16 g_wT[3][3][(size_t)NQ * DM];        // [z][part][n][k]

typedef unsigned long long ull;

// ---------------- fp32x2 helpers (qk kernel) ----------------
__device__ __forceinline__ ull pk2(float lo, float hi) {
    ull r; asm("mov.b64 %0, {%1, %2};" : "=l"(r) : "f"(lo), "f"(hi)); return r;
}
__device__ __forceinline__ void upk2(ull v, float& lo, float& hi) {
    asm("mov.b64 {%0, %1}, %2;" : "=f"(lo), "=f"(hi) : "l"(v));
}
__device__ __forceinline__ ull ffma2(ull a, ull b, ull c) {
    ull d; asm("fma.rn.f32x2 %0, %1, %2, %3;" : "=l"(d) : "l"(a), "l"(b), "l"(c)); return d;
}

// ---------------- warp MMA helpers (portable PTX, sm_80+) ----------------
__device__ __forceinline__ uint32_t smem_to_u32(const void* p) {
    uint32_t a;
    asm("{ .reg .u64 t; cvta.to.shared.u64 t, %1; cvt.u32.u64 %0, t; }" : "=r"(a) : "l"(p));
    return a;
}
__device__ __forceinline__ void ldsm_x4(uint32_t* r, uint32_t addr) {
    asm volatile("ldmatrix.sync.aligned.m8n8.x4.shared.b16 {%0,%1,%2,%3}, [%4];"
        : "=r"(r[0]), "=r"(r[1]), "=r"(r[2]), "=r"(r[3]) : "r"(addr));
}
__device__ __forceinline__ void ldsm_x2(uint32_t* r, uint32_t addr) {
    asm volatile("ldmatrix.sync.aligned.m8n8.x2.shared.b16 {%0,%1}, [%2];"
        : "=r"(r[0]), "=r"(r[1]) : "r"(addr));
}
__device__ __forceinline__ void mma16816(float* c, const uint32_t* a, const uint32_t* b) {
    asm volatile("mma.sync.aligned.m16n8k16.row.col.f32.bf16.bf16.f32 "
        "{%0,%1,%2,%3}, {%4,%5,%6,%7}, {%8,%9}, {%0,%1,%2,%3};"
        : "+f"(c[0]), "+f"(c[1]), "+f"(c[2]), "+f"(c[3])
        : "r"(a[0]), "r"(a[1]), "r"(a[2]), "r"(a[3]), "r"(b[0]), "r"(b[1]));
}

// ---------------------------------------------------------------------------
// prep: sniff mask dtype, expand mask, parallel-scan compaction, zero accums
// ---------------------------------------------------------------------------
__device__ __forceinline__ int rd_mask(int kind, const unsigned* m, int i) {
    if (kind == 0) return ((const unsigned char*)m)[i] != 0;
    if (kind == 1) return ((const int*)m)[i] != 0;
    return ((const float*)m)[i] != 0.0f;
}

__global__ void prep_kernel(const unsigned int* mraw) {
    __shared__ int wsum[32];
    __shared__ int flag_f, flag_not01;
    int t = threadIdx.x;                  // 1024 threads
    if (t == 0) { flag_f = 0; flag_not01 = 0; }
    __syncthreads();
    if (t < 512) {
        unsigned w = mraw[t];
        if (w == 0x3F800000u) atomicOr(&flag_f, 1);
        if (w > 1u)           atomicOr(&flag_not01, 1);
    }
    __syncthreads();
    int kind = flag_f ? 2 : (flag_not01 ? 0 : 1);
    int i0 = 2 * t, i1 = 2 * t + 1;
    int v0 = rd_mask(kind, mraw, i0), v1 = rd_mask(kind, mraw, i1);
    g_mask[i0] = v0; g_mask[i1] = v1;
    int s = v0 + v1, inc = s;
    int lane = t & 31, w = t >> 5;
    #pragma unroll
    for (int o = 1; o < 32; o <<= 1) {
        int n = __shfl_up_sync(0xffffffffu, inc, o);
        if (lane >= o) inc += n;
    }
    if (lane == 31) wsum[w] = inc;
    __syncthreads();
    if (t < 32) {
        int x = wsum[t];
        #pragma unroll
        for (int o = 1; o < 32; o <<= 1) {
            int n = __shfl_up_sync(0xffffffffu, x, o);
            if (t >= o) x += n;
        }
        wsum[t] = x;
    }
    __syncthreads();
    int base = (w ? wsum[w - 1] : 0) + inc - s;
    if (v0) g_cidx[base] = i0;
    if (v1) g_cidx[base + v0] = i1;
    if (t == 1023) g_cnt = wsum[31];
    g_xmean[t] = 0.0f;
    g_vmean[t] = 0.0f; g_vmean[t + 1024] = 0.0f;
}

// ---------------------------------------------------------------------------
// xmean: split rows, atomic combine.  grid (4 colblk, 16 rowblk) x 256
// ---------------------------------------------------------------------------
__global__ void xmean_kernel(const float* __restrict__ inp) {
    int k = blockIdx.x * 256 + threadIdx.x;
    int r0 = blockIdx.y * 128;
    float s = 0.0f;
    #pragma unroll 4
    for (int i = 0; i < 128; i++) s += inp[(size_t)(r0 + i) * DM + k];
    atomicAdd(&g_xmean[k], s * (1.0f / 2048.0f));
}

// vmean: split k, atomic combine.  grid (8 colblk, 16 kblk) x 256
__global__ void vmean_kernel(const float* __restrict__ Wv) {
    int c = blockIdx.x * 256 + threadIdx.x;
    int k0 = blockIdx.y * 64;
    float s = 0.0f;
    #pragma unroll 4
    for (int k = 0; k < 64; k++) s += g_xmean[k0 + k] * Wv[(size_t)(k0 + k) * NQ + c];
    atomicAdd(&g_vmean[c], s);
}

// ---------------------------------------------------------------------------
// 3-term bf16 split
// ---------------------------------------------------------------------------
__device__ __forceinline__ void split3(float v, __nv_bfloat16& a, __nv_bfloat16& b, __nv_bfloat16& c) {
    a = __float2bfloat16(v);
    float r = v - __bfloat162float(a);
    b = __float2bfloat16(r);
    float r2 = r - __bfloat162float(b);
    c = __float2bfloat16(r2);
}

// conv_x: inputs -> g_xp[0..2]    grid 2048 x 256
__global__ void conv_x_kernel(const float* __restrict__ inp) {
    size_t idx = ((size_t)blockIdx.x * 256 + threadIdx.x) * 4;
    float4 v = *(const float4*)&inp[idx];
    __nv_bfloat16 a[4], b[4], c[4];
    split3(v.x, a[0], b[0], c[0]); split3(v.y, a[1], b[1], c[1]);
    split3(v.z, a[2], b[2], c[2]); split3(v.w, a[3], b[3], c[3]);
    __nv_bfloat162* pa = (__nv_bfloat162*)&g_xp[0][idx];
    __nv_bfloat162* pb = (__nv_bfloat162*)&g_xp[1][idx];
    __nv_bfloat162* pc = (__nv_bfloat162*)&g_xp[2][idx];
    __nv_bfloat162 t;
    t.x = a[0]; t.y = a[1]; pa[0] = t;  t.x = a[2]; t.y = a[3]; pa[1] = t;
    t.x = b[0]; t.y = b[1]; pb[0] = t;  t.x = b[2]; t.y = b[3]; pb[1] = t;
    t.x = c[0]; t.y = c[1]; pc[0] = t;  t.x = c[2]; t.y = c[3]; pc[1] = t;
}

// conv_w: transpose + split W[k][n] -> g_wT[z][p][n][k]. grid (64,32,3) x (32,8)
__global__ void conv_w_kernel(const float* __restrict__ Wq,
                              const float* __restrict__ Wk,
                              const float* __restrict__ Wv) {
    __shared__ float t[32][33];
    int z = blockIdx.z;
    const float* W = (z == 0) ? Wq : (z == 1) ? Wk : Wv;
    int n0 = blockIdx.x * 32, k0 = blockIdx.y * 32;
    int tx = threadIdx.x, ty = threadIdx.y;
    #pragma unroll
    for (int i = 0; i < 4; i++)
        t[ty * 4 + i][tx] = W[(size_t)(k0 + ty * 4 + i) * NQ + n0 + tx];
    __syncthreads();
    #pragma unroll
    for (int i = 0; i < 4; i++) {
        int n = n0 + ty * 4 + i, k = k0 + tx;
        float v = t[tx][ty * 4 + i];
        __nv_bfloat16 a, b, c; split3(v, a, b, c);
        size_t off = (size_t)n * DM + k;
        g_wT[z][0][off] = a; g_wT[z][1][off] = b; g_wT[z][2][off] = c;
    }
}

// ---------------------------------------------------------------------------
// proj_mma: mma.sync bf16 GEMM. Block tile 128x128, K chunks of 32.
// 8 warps = 2(m) x 4(n), each 64x32. Split passes grouped by A part so A
// fragments load once per group. grid (16 ntile, 16 mtile, 3 z) x 256.
// smem: 6 tiles of [128][40] bf16 (pad 40 -> stride 5 x 16B, ldmatrix
// conflict-free since gcd(5,8)=1). 61,440 B dynamic.
// ---------------------------------------------------------------------------
#define LDT   40
#define TILEE (128 * LDT)
#define PROJ_SMEM_DYN (6 * TILEE * 2)

__global__ __launch_bounds__(256, 2) void proj_mma_kernel(
    const float* __restrict__ bq, const float* __restrict__ bk, const float* __restrict__ bv)
{
    extern __shared__ __align__(16) char dynsm[];
    __shared__ int cid[128];
    int cnt = g_cnt;
    int m0 = blockIdx.y * 128;
    if (m0 >= cnt) return;
    int n0 = blockIdx.x * 128;
    int z  = blockIdx.z;
    const float* bias = (z == 0) ? bq : (z == 1) ? bk : bv;
    float*       outp = (z == 0) ? g_Qc : (z == 1) ? g_Kc : g_Vc;
    // passes grouped by A part: A0x{B0,B1,B2}, A1x{B0,B1}, A2x{B0}  (Q/K)
    //                           A0x{B0,B1},    A1x{B0}             (V)
    int nB[3];
    if (z == 2) { nB[0] = 2; nB[1] = 1; nB[2] = 0; }
    else        { nB[0] = 3; nB[1] = 2; nB[2] = 1; }

    __nv_bfloat16* sm = (__nv_bfloat16*)dynsm;
    uint32_t smb = smem_to_u32(sm);

    int tid = threadIdx.x, lane = tid & 31, wid = tid >> 5;
    int wm = wid & 1, wn = wid >> 1;
    if (tid < 128) cid[tid] = g_cidx[min(m0 + tid, cnt - 1)];

    const __nv_bfloat16* xpp[3] = { g_xp[0], g_xp[1], g_xp[2] };
    const __nv_bfloat16* wpz[3] = { g_wT[z][0], g_wT[z][1], g_wT[z][2] };

    float acc[4][4][4];
    #pragma unroll
    for (int mi = 0; mi < 4; mi++)
        #pragma unroll
        for (int ni = 0; ni < 4; ni++)
            #pragma unroll
            for (int j = 0; j < 4; j++) acc[mi][ni][j] = 0.0f;

    // ldmatrix base addresses (byte addrs into smem)
    // A (x4): row = wm*64 + mi*16 + (lane&15), chunk16 = kstep*2 + (lane>>4)
    // B (x2): row = wn*32 + ni*8 + (lane&15 -> &7), chunk16 = kstep*2 + ((lane>>3)&1)
    int aRow = wm * 64 + (lane & 15);
    int aCh  = lane >> 4;
    int bRow = wn * 32 + (lane & 7);
    int bCh  = (lane >> 3) & 1;

    for (int kc = 0; kc < 32; kc++) {
        __syncthreads();
        // fill 6 tiles: 3 A parts (rows via cid) + 3 B parts, 32 k each
        #pragma unroll
        for (int it = 0; it < 12; it++) {
            int u    = it * 256 + tid;
            int isB  = u >= 1536;
            int v    = u - (isB ? 1536 : 0);
            int part = v >> 9;
            int rr   = v & 511;
            int row  = rr >> 2;
            int ch   = rr & 3;
            const __nv_bfloat16* src = isB
                ? (wpz[part] + ((size_t)(n0 + row) << 10))
                : (xpp[part] + ((size_t)cid[row] << 10));
            uint4 val = ((const uint4*)(src + (kc << 5)))[ch];
            *(uint4*)&sm[((isB ? 3 : 0) + part) * TILEE + row * LDT + ch * 8] = val;
        }
        __syncthreads();

        #pragma unroll
        for (int kstep = 0; kstep < 2; kstep++) {
            #pragma unroll
            for (int ai = 0; ai < 3; ai++) {
                if (nB[ai] == 0) break;
                uint32_t a[4][4];
                uint32_t abase = smb + (ai * TILEE) * 2;
                #pragma unroll
                for (int mi = 0; mi < 4; mi++)
                    ldsm_x4(a[mi], abase + ((aRow + mi * 16) * LDT) * 2
                                         + (kstep * 2 + aCh) * 16);
                #pragma unroll
                for (int bi = 0; bi < 3; bi++) {
                    if (bi >= nB[ai]) break;
                    uint32_t bbase = smb + ((3 + bi) * TILEE) * 2;
                    uint32_t b[4][2];
                    #pragma unroll
                    for (int ni = 0; ni < 4; ni++)
                        ldsm_x2(b[ni], bbase + ((bRow + ni * 8) * LDT) * 2
                                             + (kstep * 2 + bCh) * 16);
                    #pragma unroll
                    for (int mi = 0; mi < 4; mi++)
                        #pragma unroll
                        for (int ni = 0; ni < 4; ni++)
                            mma16816(acc[mi][ni], a[mi], b[ni]);
                }
            }
        }
    }

    // epilogue: c0,c1 -> (row=lane>>2, col=(lane&3)*2), c2,c3 -> row+8
    int rbase = m0 + wm * 64 + (lane >> 2);
    int cbase = n0 + wn * 32 + (lane & 3) * 2;
    #pragma unroll
    for (int mi = 0; mi < 4; mi++) {
        #pragma unroll
        for (int half = 0; half < 2; half++) {
            int m = rbase + mi * 16 + half * 8;
            if (m >= cnt) continue;
            float* orow = &outp[(size_t)m * NQ];
            #pragma unroll
            for (int ni = 0; ni < 4; ni++) {
                int c = cbase + ni * 8;
                float2 bb = *(const float2*)&bias[c];
                float2 r;
                r.x = acc[mi][ni][half * 2 + 0] + bb.x;
                r.y = acc[mi][ni][half * 2 + 1] + bb.y;
                *(float2*)&orow[c] = r;
            }
        }
    }
}

// ---------------------------------------------------------------------------
// QK^T + running argmin (fp32 FFMA2, precision-critical)
// ---------------------------------------------------------------------------
__global__ __launch_bounds__(256) void qk_kernel() {
    __shared__ float Qs[128][68];
    __shared__ float Ks[16][132];
    int cnt = g_cnt;
    int s0 = blockIdx.x * 64;
    if (s0 >= cnt) return;
    int h = blockIdx.y;
    int hb = h * HD;
    int tid = threadIdx.x, tx = tid & 15, ty = tid >> 4;

    #pragma unroll
    for (int it = 0; it < 8; it++) {
        int idx = it * 256 + tid;
        int d4 = idx >> 6, row = idx & 63;
        int r = min(s0 + row, cnt - 1);
        float4 v = *(const float4*)&g_Qc[(size_t)r * NQ + hb + d4 * 4];
        Qs[d4 * 4 + 0][row] = v.x; Qs[d4 * 4 + 1][row] = v.y;
        Qs[d4 * 4 + 2][row] = v.z; Qs[d4 * 4 + 3][row] = v.w;
    }

    float rmin[4] = {FLT_MAX, FLT_MAX, FLT_MAX, FLT_MAX};
    int   ridx[4] = {0, 0, 0, 0};

    int ttiles = (cnt + 127) >> 7;
    for (int tt = 0; tt < ttiles; tt++) {
        int t0 = tt * 128;
        ull acc[4][4];
        #pragma unroll
        for (int i = 0; i < 4; i++)
            #pragma unroll
            for (int j = 0; j < 4; j++) acc[i][j] = 0ull;

        for (int dc = 0; dc < 8; dc++) {
            __syncthreads();
            #pragma unroll
            for (int it = 0; it < 2; it++) {
                int idx = it * 256 + tid;
                int d4 = idx >> 7, row = idx & 127;
                int r = min(t0 + row, cnt - 1);
                float4 v = *(const float4*)&g_Kc[(size_t)r * NQ + hb + dc * 16 + d4 * 4];
                Ks[d4 * 4 + 0][row] = v.x; Ks[d4 * 4 + 1][row] = v.y;
                Ks[d4 * 4 + 2][row] = v.z; Ks[d4 * 4 + 3][row] = v.w;
            }
            __syncthreads();
            #pragma unroll
            for (int k = 0; k < 16; k++) {
                float4 a = *(const float4*)&Qs[dc * 16 + k][ty * 4];
                ulonglong2 b01 = *(const ulonglong2*)&Ks[k][tx * 8];
                ulonglong2 b23 = *(const ulonglong2*)&Ks[k][tx * 8 + 4];
                float av[4] = {a.x, a.y, a.z, a.w};
                #pragma unroll
                for (int i = 0; i < 4; i++) {
                    ull ai = pk2(av[i], av[i]);
                    acc[i][0] = ffma2(ai, b01.x, acc[i][0]);
                    acc[i][1] = ffma2(ai, b01.y, acc[i][1]);
                    acc[i][2] = ffma2(ai, b23.x, acc[i][2]);
                    acc[i][3] = ffma2(ai, b23.y, acc[i][3]);
                }
            }
        }
        #pragma unroll
        for (int i = 0; i < 4; i++) {
            #pragma unroll
            for (int j = 0; j < 4; j++) {
                float lo, hi; upk2(acc[i][j], lo, hi);
                int c0 = t0 + tx * 8 + 2 * j;
                if (c0 < cnt     && lo < rmin[i]) { rmin[i] = lo; ridx[i] = c0; }
                if (c0 + 1 < cnt && hi < rmin[i]) { rmin[i] = hi; ridx[i] = c0 + 1; }
            }
        }
    }

    __syncthreads();
    float* Rm = &Qs[0][0];
    int*   Ri = (int*)&Qs[32][0];
    #pragma unroll
    for (int i = 0; i < 4; i++) {
        Rm[(ty * 4 + i) * 16 + tx] = rmin[i];
        Ri[(ty * 4 + i) * 16 + tx] = ridx[i];
    }
    __syncthreads();
    if (tid < 64) {
        int srow = s0 + tid;
        if (srow < cnt) {
            float bm = Rm[tid * 16]; int bi = Ri[tid * 16];
            #pragma unroll
            for (int x = 1; x < 16; x++) {
                float v = Rm[tid * 16 + x];
                if (v < bm) { bm = v; bi = Ri[tid * 16 + x]; }
            }
            g_argT[h * SEQ + g_cidx[srow]] = bi;
        }
    }
}

// ---------------------------------------------------------------------------
// output: masked rows gather V[t*], unmasked rows take vmean + bv
// ---------------------------------------------------------------------------
__global__ void out_kernel(float* __restrict__ out, const float* __restrict__ bv) {
    int s = blockIdx.x, tid = threadIdx.x;
    int ms = g_mask[s];
    #pragma unroll
    for (int rep = 0; rep < 2; rep++) {
        int c = (rep * 256 + tid) * 4;
        float4 v;
        if (ms) {
            int hh = c >> 7;
            int tc = g_argT[hh * SEQ + s];
            v = *(const float4*)&g_Vc[(size_t)tc * NQ + c];
        } else {
            float4 a = *(const float4*)&g_vmean[c];
            float4 b = *(const float4*)&bv[c];
            v.x = a.x + b.x; v.y = a.y + b.y; v.z = a.z + b.z; v.w = a.w + b.w;
        }
        *(float4*)&out[(size_t)s * NQ + c] = v;
    }
}

// ---------------------------------------------------------------------------
extern "C" void kernel_launch(void* const* d_in, const int* in_sizes, int n_in,
                              void* d_out, int out_size)
{
    const float* inp = (const float*)d_in[0];
    const void*  msk = d_in[1];
    const float* Wq  = (const float*)d_in[2];
    const float* bq  = (const float*)d_in[3];
    const float* Wk  = (const float*)d_in[4];
    const float* bk  = (const float*)d_in[5];
    const float* Wv  = (const float*)d_in[6];
    const float* bv  = (const float*)d_in[7];
    float* out = (float*)d_out;

    cudaFuncSetAttribute(proj_mma_kernel,
                         cudaFuncAttributeMaxDynamicSharedMemorySize, PROJ_SMEM_DYN);

    prep_kernel<<<1, 1024>>>((const unsigned int*)msk);
    conv_x_kernel<<<2048, 256>>>(inp);
    conv_w_kernel<<<dim3(64, 32, 3), dim3(32, 8)>>>(Wq, Wk, Wv);
    xmean_kernel<<<dim3(4, 16), 256>>>(inp);
    proj_mma_kernel<<<dim3(16, 16, 3), 256, PROJ_SMEM_DYN>>>(bq, bk, bv);
    vmean_kernel<<<dim3(8, 16), 256>>>(Wv);
    qk_kernel<<<dim3(32, 16), 256>>>();
    out_kernel<<<SEQ, 256>>>(out, bv);
}

// round 11
// speedup vs baseline: 1.7485x; 1.2695x over previous
#include <cuda_runtime.h>
#include <cuda_bf16.h>
#include <cfloat>
#include <cstdint>
#include <math.h>

// ---------------------------------------------------------------------------
// AttentionLayer: inputs[2048,1024] -> out[2048,2048]
//   m_s False row -> exact uniform softmax -> out = xmean @ Wv + bv
//   m_s True  row -> exact one-hot at argmin_t raw_score over m_t True
// Projections AND QK^T on mma.sync bf16 with 3-term splitting (tcgen05 PTX is
// rejected by this harness's sm_103 ptxas target). Argmin via sortable-key
// atomicMin.
// ---------------------------------------------------------------------------

#define SEQ   2048
#define DM    1024
#define NQ    2048
#define HN    16
#define HD    128

typedef unsigned long long ull;

__device__ float g_Vc[(size_t)SEQ * NQ];
__device__ int   g_cidx[SEQ];
__device__ int   g_mask[SEQ];
__device__ int   g_cnt;
__device__ ull   g_best[HN * SEQ];          // per (head, ORIGINAL s): packed (score,t)
__device__ float g_xmean[DM];
__device__ float g_vmean[NQ];
// bf16 3-term splits
__device__ __nv_bfloat16 g_xp[3][(size_t)SEQ * DM];       // x parts [s][k]
__device__ __nv_bfloat16 g_wT[3][3][(size_t)NQ * DM];     // [z][part][n][k]
__device__ __nv_bfloat16 g_Qp[3][(size_t)SEQ * NQ];       // Q parts [s][h*128+d]
__device__ __nv_bfloat16 g_Kp[3][(size_t)SEQ * NQ];       // K parts [t][h*128+d]

// ---------------- warp MMA helpers (portable PTX, sm_80+) ----------------
__device__ __forceinline__ uint32_t smem_to_u32(const void* p) {
    uint32_t a;
    asm("{ .reg .u64 t; cvta.to.shared.u64 t, %1; cvt.u32.u64 %0, t; }" : "=r"(a) : "l"(p));
    return a;
}
__device__ __forceinline__ void ldsm_x4(uint32_t* r, uint32_t addr) {
    asm volatile("ldmatrix.sync.aligned.m8n8.x4.shared.b16 {%0,%1,%2,%3}, [%4];"
        : "=r"(r[0]), "=r"(r[1]), "=r"(r[2]), "=r"(r[3]) : "r"(addr));
}
__device__ __forceinline__ void ldsm_x2(uint32_t* r, uint32_t addr) {
    asm volatile("ldmatrix.sync.aligned.m8n8.x2.shared.b16 {%0,%1}, [%2];"
        : "=r"(r[0]), "=r"(r[1]) : "r"(addr));
}
__device__ __forceinline__ void mma16816(float* c, const uint32_t* a, const uint32_t* b) {
    asm volatile("mma.sync.aligned.m16n8k16.row.col.f32.bf16.bf16.f32 "
        "{%0,%1,%2,%3}, {%4,%5,%6,%7}, {%8,%9}, {%0,%1,%2,%3};"
        : "+f"(c[0]), "+f"(c[1]), "+f"(c[2]), "+f"(c[3])
        : "r"(a[0]), "r"(a[1]), "r"(a[2]), "r"(a[3]), "r"(b[0]), "r"(b[1]));
}

// ---------------------------------------------------------------------------
// prep: sniff mask dtype, expand mask, parallel-scan compaction, init accums
// ---------------------------------------------------------------------------
__device__ __forceinline__ int rd_mask(int kind, const unsigned* m, int i) {
    if (kind == 0) return ((const unsigned char*)m)[i] != 0;
    if (kind == 1) return ((const int*)m)[i] != 0;
    return ((const float*)m)[i] != 0.0f;
}

__global__ void prep_kernel(const unsigned int* mraw) {
    __shared__ int wsum[32];
    __shared__ int flag_f, flag_not01;
    int t = threadIdx.x;                  // 1024 threads
    if (t == 0) { flag_f = 0; flag_not01 = 0; }
    __syncthreads();
    if (t < 512) {
        unsigned w = mraw[t];
        if (w == 0x3F800000u) atomicOr(&flag_f, 1);
        if (w > 1u)           atomicOr(&flag_not01, 1);
    }
    __syncthreads();
    int kind = flag_f ? 2 : (flag_not01 ? 0 : 1);
    int i0 = 2 * t, i1 = 2 * t + 1;
    int v0 = rd_mask(kind, mraw, i0), v1 = rd_mask(kind, mraw, i1);
    g_mask[i0] = v0; g_mask[i1] = v1;
    int s = v0 + v1, inc = s;
    int lane = t & 31, w = t >> 5;
    #pragma unroll
    for (int o = 1; o < 32; o <<= 1) {
        int n = __shfl_up_sync(0xffffffffu, inc, o);
        if (lane >= o) inc += n;
    }
    if (lane == 31) wsum[w] = inc;
    __syncthreads();
    if (t < 32) {
        int x = wsum[t];
        #pragma unroll
        for (int o = 1; o < 32; o <<= 1) {
            int n = __shfl_up_sync(0xffffffffu, x, o);
            if (t >= o) x += n;
        }
        wsum[t] = x;
    }
    __syncthreads();
    int base = (w ? wsum[w - 1] : 0) + inc - s;
    if (v0) g_cidx[base] = i0;
    if (v1) g_cidx[base + v0] = i1;
    if (t == 1023) g_cnt = wsum[31];
    g_xmean[t] = 0.0f;
    g_vmean[t] = 0.0f; g_vmean[t + 1024] = 0.0f;
    #pragma unroll
    for (int i = 0; i < HN * SEQ / 1024; i++) g_best[i * 1024 + t] = ~0ull;
}

// ---------------------------------------------------------------------------
// xmean: 16 contiguous rows per block, fully coalesced.  grid 128 x 256
// ---------------------------------------------------------------------------
__global__ void xmean_kernel(const float* __restrict__ inp) {
    int r0 = blockIdx.x * 16;
    int c  = threadIdx.x * 4;
    float4 s = {0.f, 0.f, 0.f, 0.f};
    #pragma unroll
    for (int r = 0; r < 16; r++) {
        float4 v = *(const float4*)&inp[(size_t)(r0 + r) * DM + c];
        s.x += v.x; s.y += v.y; s.z += v.z; s.w += v.w;
    }
    const float sc = 1.0f / 2048.0f;
    atomicAdd(&g_xmean[c + 0], s.x * sc);
    atomicAdd(&g_xmean[c + 1], s.y * sc);
    atomicAdd(&g_xmean[c + 2], s.z * sc);
    atomicAdd(&g_xmean[c + 3], s.w * sc);
}

// vmean: split k, atomic combine.  grid (8 colblk, 16 kblk) x 256
__global__ void vmean_kernel(const float* __restrict__ Wv) {
    int c = blockIdx.x * 256 + threadIdx.x;
    int k0 = blockIdx.y * 64;
    float s = 0.0f;
    #pragma unroll 4
    for (int k = 0; k < 64; k++) s += g_xmean[k0 + k] * Wv[(size_t)(k0 + k) * NQ + c];
    atomicAdd(&g_vmean[c], s);
}

// ---------------------------------------------------------------------------
// 3-term bf16 split
// ---------------------------------------------------------------------------
__device__ __forceinline__ void split3(float v, __nv_bfloat16& a, __nv_bfloat16& b, __nv_bfloat16& c) {
    a = __float2bfloat16(v);
    float r = v - __bfloat162float(a);
    b = __float2bfloat16(r);
    float r2 = r - __bfloat162float(b);
    c = __float2bfloat16(r2);
}

// conv_x: inputs -> g_xp[0..2]    grid 2048 x 256
__global__ void conv_x_kernel(const float* __restrict__ inp) {
    size_t idx = ((size_t)blockIdx.x * 256 + threadIdx.x) * 4;
    float4 v = *(const float4*)&inp[idx];
    __nv_bfloat16 a[4], b[4], c[4];
    split3(v.x, a[0], b[0], c[0]); split3(v.y, a[1], b[1], c[1]);
    split3(v.z, a[2], b[2], c[2]); split3(v.w, a[3], b[3], c[3]);
    __nv_bfloat162* pa = (__nv_bfloat162*)&g_xp[0][idx];
    __nv_bfloat162* pb = (__nv_bfloat162*)&g_xp[1][idx];
    __nv_bfloat162* pc = (__nv_bfloat162*)&g_xp[2][idx];
    __nv_bfloat162 t;
    t.x = a[0]; t.y = a[1]; pa[0] = t;  t.x = a[2]; t.y = a[3]; pa[1] = t;
    t.x = b[0]; t.y = b[1]; pb[0] = t;  t.x = b[2]; t.y = b[3]; pb[1] = t;
    t.x = c[0]; t.y = c[1]; pc[0] = t;  t.x = c[2]; t.y = c[3]; pc[1] = t;
}

// conv_w: transpose + split W[k][n] -> g_wT[z][p][n][k]. grid (64,32,3) x (32,8)
__global__ void conv_w_kernel(const float* __restrict__ Wq,
                              const float* __restrict__ Wk,
                              const float* __restrict__ Wv) {
    __shared__ float t[32][33];
    int z = blockIdx.z;
    const float* W = (z == 0) ? Wq : (z == 1) ? Wk : Wv;
    int n0 = blockIdx.x * 32, k0 = blockIdx.y * 32;
    int tx = threadIdx.x, ty = threadIdx.y;
    #pragma unroll
    for (int i = 0; i < 4; i++)
        t[ty * 4 + i][tx] = W[(size_t)(k0 + ty * 4 + i) * NQ + n0 + tx];
    __syncthreads();
    #pragma unroll
    for (int i = 0; i < 4; i++) {
        int n = n0 + ty * 4 + i, k = k0 + tx;
        float v = t[tx][ty * 4 + i];
        __nv_bfloat16 a, b, c; split3(v, a, b, c);
        size_t off = (size_t)n * DM + k;
        g_wT[z][0][off] = a; g_wT[z][1][off] = b; g_wT[z][2][off] = c;
    }
}

// ---------------------------------------------------------------------------
// proj_mma: mma.sync bf16 GEMM. Block tile 128x128, K chunks of 32.
// 8 warps = 2(m) x 4(n), each 64x32. grid (16 ntile, 16 mtile, 3 z) x 256.
// z=0/1 (Q/K): epilogue splits result into 3 bf16 planes for qk_mma.
// z=2 (V): fp32 store for the final gather.
// ---------------------------------------------------------------------------
#define LDT   40
#define TILEE (128 * LDT)
#define PROJ_SMEM_DYN (6 * TILEE * 2)

__global__ __launch_bounds__(256, 2) void proj_mma_kernel(
    const float* __restrict__ bq, const float* __restrict__ bk, const float* __restrict__ bv)
{
    extern __shared__ __align__(16) char dynsm[];
    __shared__ int cid[128];
    int cnt = g_cnt;
    int m0 = blockIdx.y * 128;
    if (m0 >= cnt) return;
    int n0 = blockIdx.x * 128;
    int z  = blockIdx.z;
    const float* bias = (z == 0) ? bq : (z == 1) ? bk : bv;
    int nB[3];
    if (z == 2) { nB[0] = 2; nB[1] = 1; nB[2] = 0; }
    else        { nB[0] = 3; nB[1] = 2; nB[2] = 1; }

    __nv_bfloat16* sm = (__nv_bfloat16*)dynsm;
    uint32_t smb = smem_to_u32(sm);

    int tid = threadIdx.x, lane = tid & 31, wid = tid >> 5;
    int wm = wid & 1, wn = wid >> 1;
    if (tid < 128) cid[tid] = g_cidx[min(m0 + tid, cnt - 1)];

    const __nv_bfloat16* xpp[3] = { g_xp[0], g_xp[1], g_xp[2] };
    const __nv_bfloat16* wpz[3] = { g_wT[z][0], g_wT[z][1], g_wT[z][2] };

    float acc[4][4][4];
    #pragma unroll
    for (int mi = 0; mi < 4; mi++)
        #pragma unroll
        for (int ni = 0; ni < 4; ni++)
            #pragma unroll
            for (int j = 0; j < 4; j++) acc[mi][ni][j] = 0.0f;

    int aRow = wm * 64 + (lane & 15);
    int aCh  = lane >> 4;
    int bRow = wn * 32 + (lane & 7);
    int bCh  = (lane >> 3) & 1;

    for (int kc = 0; kc < 32; kc++) {
        __syncthreads();
        #pragma unroll
        for (int it = 0; it < 12; it++) {
            int u    = it * 256 + tid;
            int isB  = u >= 1536;
            int v    = u - (isB ? 1536 : 0);
            int part = v >> 9;
            int rr   = v & 511;
            int row  = rr >> 2;
            int ch   = rr & 3;
            const __nv_bfloat16* src = isB
                ? (wpz[part] + ((size_t)(n0 + row) << 10))
                : (xpp[part] + ((size_t)cid[row] << 10));
            uint4 val = ((const uint4*)(src + (kc << 5)))[ch];
            *(uint4*)&sm[((isB ? 3 : 0) + part) * TILEE + row * LDT + ch * 8] = val;
        }
        __syncthreads();

        #pragma unroll
        for (int kstep = 0; kstep < 2; kstep++) {
            #pragma unroll
            for (int ai = 0; ai < 3; ai++) {
                if (nB[ai] == 0) break;
                uint32_t a[4][4];
                uint32_t abase = smb + (ai * TILEE) * 2;
                #pragma unroll
                for (int mi = 0; mi < 4; mi++)
                    ldsm_x4(a[mi], abase + ((aRow + mi * 16) * LDT) * 2
                                         + (kstep * 2 + aCh) * 16);
                #pragma unroll
                for (int bi = 0; bi < 3; bi++) {
                    if (bi >= nB[ai]) break;
                    uint32_t bbase = smb + ((3 + bi) * TILEE) * 2;
                    uint32_t b[4][2];
                    #pragma unroll
                    for (int ni = 0; ni < 4; ni++)
                        ldsm_x2(b[ni], bbase + ((bRow + ni * 8) * LDT) * 2
                                             + (kstep * 2 + bCh) * 16);
                    #pragma unroll
                    for (int mi = 0; mi < 4; mi++)
                        #pragma unroll
                        for (int ni = 0; ni < 4; ni++)
                            mma16816(acc[mi][ni], a[mi], b[ni]);
                }
            }
        }
    }

    // epilogue
    int rbase = m0 + wm * 64 + (lane >> 2);
    int cbase = n0 + wn * 32 + (lane & 3) * 2;
    __nv_bfloat16* pp0 = (z == 0) ? g_Qp[0] : g_Kp[0];
    __nv_bfloat16* pp1 = (z == 0) ? g_Qp[1] : g_Kp[1];
    __nv_bfloat16* pp2 = (z == 0) ? g_Qp[2] : g_Kp[2];
    #pragma unroll
    for (int mi = 0; mi < 4; mi++) {
        #pragma unroll
        for (int half = 0; half < 2; half++) {
            int m = rbase + mi * 16 + half * 8;
            if (m >= cnt) continue;
            size_t rb = (size_t)m * NQ;
            #pragma unroll
            for (int ni = 0; ni < 4; ni++) {
                int c = cbase + ni * 8;
                float2 bb = *(const float2*)&bias[c];
                float v0 = acc[mi][ni][half * 2 + 0] + bb.x;
                float v1 = acc[mi][ni][half * 2 + 1] + bb.y;
                if (z == 2) {
                    float2 r; r.x = v0; r.y = v1;
                    *(float2*)&g_Vc[rb + c] = r;
                } else {
                    __nv_bfloat16 a0, b0, c0, a1, b1, c1;
                    split3(v0, a0, b0, c0); split3(v1, a1, b1, c1);
                    __nv_bfloat162 t;
                    t.x = a0; t.y = a1; *(__nv_bfloat162*)&pp0[rb + c] = t;
                    t.x = b0; t.y = b1; *(__nv_bfloat162*)&pp1[rb + c] = t;
                    t.x = c0; t.y = c1; *(__nv_bfloat162*)&pp2[rb + c] = t;
                }
            }
        }
    }
}

// ---------------------------------------------------------------------------
// qk_mma: scores S[s][t] per head via 6 split products (fp32 accum), then
// argmin via sortable-key atomicMin. grid (16 ttile, 16 stile, 16 h) x 256.
// ---------------------------------------------------------------------------
#define QK_SMEM_DYN (6 * TILEE * 2 + 128 * 8)

__global__ __launch_bounds__(256, 2) void qk_mma_kernel() {
    extern __shared__ __align__(16) char dynsm[];
    int cnt = g_cnt;
    int t0 = blockIdx.x * 128;
    int s0 = blockIdx.y * 128;
    if (s0 >= cnt || t0 >= cnt) return;
    int h = blockIdx.z;
    int hb = h * HD;

    __nv_bfloat16* sm = (__nv_bfloat16*)dynsm;
    ull* red = (ull*)(dynsm + 6 * TILEE * 2);
    uint32_t smb = smem_to_u32(sm);

    int tid = threadIdx.x, lane = tid & 31, wid = tid >> 5;
    int wm = wid & 1, wn = wid >> 1;
    if (tid < 128) red[tid] = ~0ull;

    float acc[4][4][4];
    #pragma unroll
    for (int mi = 0; mi < 4; mi++)
        #pragma unroll
        for (int ni = 0; ni < 4; ni++)
            #pragma unroll
            for (int j = 0; j < 4; j++) acc[mi][ni][j] = 0.0f;

    int aRow = wm * 64 + (lane & 15);
    int aCh  = lane >> 4;
    int bRow = wn * 32 + (lane & 7);
    int bCh  = (lane >> 3) & 1;
    const int nB[3] = {3, 2, 1};

    for (int kc = 0; kc < 4; kc++) {        // HD=128 in 4 chunks of 32
        __syncthreads();
        #pragma unroll
        for (int it = 0; it < 12; it++) {
            int u    = it * 256 + tid;
            int isB  = u >= 1536;
            int v    = u - (isB ? 1536 : 0);
            int part = v >> 9;
            int rr   = v & 511;
            int row  = rr >> 2;
            int ch   = rr & 3;
            const __nv_bfloat16* src = isB
                ? (g_Kp[part] + (size_t)min(t0 + row, cnt - 1) * NQ)
                : (g_Qp[part] + (size_t)min(s0 + row, cnt - 1) * NQ);
            uint4 val = ((const uint4*)(src + hb + kc * 32))[ch];
            *(uint4*)&sm[((isB ? 3 : 0) + part) * TILEE + row * LDT + ch * 8] = val;
        }
        __syncthreads();

        #pragma unroll
        for (int kstep = 0; kstep < 2; kstep++) {
            #pragma unroll
            for (int ai = 0; ai < 3; ai++) {
                uint32_t a[4][4];
                uint32_t abase = smb + (ai * TILEE) * 2;
                #pragma unroll
                for (int mi = 0; mi < 4; mi++)
                    ldsm_x4(a[mi], abase + ((aRow + mi * 16) * LDT) * 2
                                         + (kstep * 2 + aCh) * 16);
                #pragma unroll
                for (int bi = 0; bi < 3; bi++) {
                    if (bi >= nB[ai]) break;
                    uint32_t bbase = smb + ((3 + bi) * TILEE) * 2;
                    uint32_t b[4][2];
                    #pragma unroll
                    for (int ni = 0; ni < 4; ni++)
                        ldsm_x2(b[ni], bbase + ((bRow + ni * 8) * LDT) * 2
                                             + (kstep * 2 + bCh) * 16);
                    #pragma unroll
                    for (int mi = 0; mi < 4; mi++)
                        #pragma unroll
                        for (int ni = 0; ni < 4; ni++)
                            mma16816(acc[mi][ni], a[mi], b[ni]);
                }
            }
        }
    }

    // per-thread argmin fold over its 8 cols, per 8 rows -> smem atomicMin
    #pragma unroll
    for (int mi = 0; mi < 4; mi++) {
        #pragma unroll
        for (int half = 0; half < 2; half++) {
            int rloc = wm * 64 + mi * 16 + half * 8 + (lane >> 2);
            float bm = FLT_MAX; int bt = 0;
            #pragma unroll
            for (int ni = 0; ni < 4; ni++) {
                #pragma unroll
                for (int j = 0; j < 2; j++) {
                    float v = acc[mi][ni][half * 2 + j];
                    int t = t0 + wn * 32 + ni * 8 + (lane & 3) * 2 + j;
                    if (t < cnt && v < bm) { bm = v; bt = t; }
                }
            }
            if (bm < FLT_MAX) {
                uint32_t u = __float_as_uint(bm);
                u = (u & 0x80000000u) ? ~u : (u | 0x80000000u);
                ull key = ((ull)u << 32) | (uint32_t)bt;
                atomicMin(&red[rloc], key);
            }
        }
    }
    __syncthreads();
    if (tid < 128) {
        int s = s0 + tid;
        if (s < cnt) atomicMin(&g_best[h * SEQ + g_cidx[s]], red[tid]);
    }
}

// ---------------------------------------------------------------------------
// output: masked rows gather V[t*], unmasked rows take vmean + bv
// ---------------------------------------------------------------------------
__global__ void out_kernel(float* __restrict__ out, const float* __restrict__ bv) {
    int s = blockIdx.x, tid = threadIdx.x;
    int ms = g_mask[s];
    #pragma unroll
    for (int rep = 0; rep < 2; rep++) {
        int c = (rep * 256 + tid) * 4;
        float4 v;
        if (ms) {
            int hh = c >> 7;
            int tc = (int)(g_best[hh * SEQ + s] & 0xFFFFFFFFull);
            v = *(const float4*)&g_Vc[(size_t)tc * NQ + c];
        } else {
            float4 a = *(const float4*)&g_vmean[c];
            float4 b = *(const float4*)&bv[c];
            v.x = a.x + b.x; v.y = a.y + b.y; v.z = a.z + b.z; v.w = a.w + b.w;
        }
        *(float4*)&out[(size_t)s * NQ + c] = v;
    }
}

// ---------------------------------------------------------------------------
extern "C" void kernel_launch(void* const* d_in, const int* in_sizes, int n_in,
                              void* d_out, int out_size)
{
    const float* inp = (const float*)d_in[0];
    const void*  msk = d_in[1];
    const float* Wq  = (const float*)d_in[2];
    const float* bq  = (const float*)d_in[3];
    const float* Wk  = (const float*)d_in[4];
    const float* bk  = (const float*)d_in[5];
    const float* Wv  = (const float*)d_in[6];
    const float* bv  = (const float*)d_in[7];
    float* out = (float*)d_out;

    cudaFuncSetAttribute(proj_mma_kernel,
                         cudaFuncAttributeMaxDynamicSharedMemorySize, PROJ_SMEM_DYN);
    cudaFuncSetAttribute(qk_mma_kernel,
                         cudaFuncAttributeMaxDynamicSharedMemorySize, QK_SMEM_DYN);

    prep_kernel<<<1, 1024>>>((const unsigned int*)msk);
    conv_x_kernel<<<2048, 256>>>(inp);
    conv_w_kernel<<<dim3(64, 32, 3), dim3(32, 8)>>>(Wq, Wk, Wv);
    xmean_kernel<<<128, 256>>>(inp);
    proj_mma_kernel<<<dim3(16, 16, 3), 256, PROJ_SMEM_DYN>>>(bq, bk, bv);
    vmean_kernel<<<dim3(8, 16), 256>>>(Wv);
    qk_mma_kernel<<<dim3(16, 16, 16), 256, QK_SMEM_DYN>>>();
    out_kernel<<<SEQ, 256>>>(out, bv);
}